// round 16
// baseline (speedup 1.0000x reference)
#include <cuda_runtime.h>
#include <cuda_bf16.h>
#include <math.h>
#include <stdint.h>

// Problem dims (fixed by the reference)
#define TB_B 2
#define TB_S 2048
#define TB_D 1024
#define TB_F 4096
#define TB_H 16
#define TB_HD 64
#define TB_T (TB_B * TB_S)   // 4096 tokens
#define TB_D2 (2 * TB_D)     // 2048 ([hi|lo] split layout)
#define TB_F2 (2 * TB_F)     // 8192

#if defined(__CUDA_ARCH_FEAT_SM103_ALL) || defined(__CUDA_ARCH_FEAT_SM100_ALL)
#define HAS_TCGEN05 1
#else
#define HAS_TCGEN05 0
#endif

// ---------------- scratch ----------------------------------------------------
__device__ __nv_bfloat16 g_xn3 [(size_t)TB_T * TB_D2];
__device__ __nv_bfloat16 g_att3[(size_t)TB_T * TB_D2];
__device__ __nv_bfloat16 g_ff3 [(size_t)TB_T * TB_F2];
__device__ float g_h [(size_t)TB_T * TB_D];
__device__ __nv_bfloat16 g_q3 [(size_t)TB_T * TB_H * 128];
__device__ __nv_bfloat16 g_k3 [(size_t)TB_T * TB_H * 128];
__device__ __nv_bfloat16 g_vt3[(size_t)TB_B * TB_H * 128 * TB_S];
__device__ __nv_bfloat16 g_wq3 [(size_t)TB_D * TB_D2];
__device__ __nv_bfloat16 g_wk3 [(size_t)TB_D * TB_D2];
__device__ __nv_bfloat16 g_wv3 [(size_t)TB_D * TB_D2];
__device__ __nv_bfloat16 g_wo3 [(size_t)TB_D * TB_D2];
__device__ __nv_bfloat16 g_win3[(size_t)TB_F * TB_D2];
__device__ __nv_bfloat16 g_wout3[(size_t)TB_D * TB_F2];

// ---------------- helpers ----------------------------------------------------
__device__ __forceinline__ uint32_t smem_u32(const void* p) {
    uint32_t a;
    asm("{ .reg .u64 t; cvta.to.shared.u64 t, %1; cvt.u32.u64 %0, t; }" : "=r"(a) : "l"(p));
    return a;
}
__device__ __forceinline__ void split_bf16(float x, __nv_bfloat16& hi, __nv_bfloat16& lo) {
    hi = __float2bfloat16(x);
    lo = __float2bfloat16(x - __bfloat162float(hi));
}
__device__ __forceinline__ float gelu_tanh(float v) {
    const float c = 0.79788456080286535588f;
    float t = c * (v + 0.044715f * v * v * v);
    return 0.5f * v * (1.0f + tanhf(t));
}
__device__ __forceinline__ uint2 pack4bf(__nv_bfloat16 a, __nv_bfloat16 b,
                                         __nv_bfloat16 c, __nv_bfloat16 d) {
    uint2 r;
    r.x = (uint32_t)__bfloat16_as_ushort(a) | ((uint32_t)__bfloat16_as_ushort(b) << 16);
    r.y = (uint32_t)__bfloat16_as_ushort(c) | ((uint32_t)__bfloat16_as_ushort(d) << 16);
    return r;
}

#if HAS_TCGEN05
__device__ __forceinline__ uint32_t elect_one() {
    uint32_t p;
    asm volatile("{ .reg .pred p; elect.sync _|p, 0xFFFFFFFF; selp.b32 %0, 1, 0, p; }" : "=r"(p));
    return p;
}
__device__ __forceinline__ void mbar_init(uint32_t a, uint32_t cnt) {
    asm volatile("mbarrier.init.shared.b64 [%0], %1;" :: "r"(a), "r"(cnt) : "memory");
}
__device__ __forceinline__ void mbar_arrive(uint32_t a) {
    asm volatile("mbarrier.arrive.shared.b64 _, [%0];" :: "r"(a) : "memory");
}
__device__ __forceinline__ void mbar_wait(uint32_t a, uint32_t parity) {
    asm volatile(
        "{\n\t.reg .pred P;\n\t"
        "LW%=:\n\t"
        "mbarrier.try_wait.parity.acquire.cta.shared::cta.b64 P, [%0], %1, 0x989680;\n\t"
        "@P bra LD%=;\n\t"
        "bra LW%=;\n\t"
        "LD%=:\n\t}"
        :: "r"(a), "r"(parity) : "memory");
}
__device__ __forceinline__ void cp_async16(uint32_t dst, const void* src) {
    asm volatile("cp.async.cg.shared.global [%0], [%1], 16;" :: "r"(dst), "l"(src) : "memory");
}
__device__ __forceinline__ void cp_async_arrive(uint32_t mbar) {
    asm volatile("cp.async.mbarrier.arrive.noinc.shared::cta.b64 [%0];" :: "r"(mbar) : "memory");
}
__device__ __forceinline__ void mma_f16_ss(uint32_t d, uint64_t ad, uint64_t bd,
                                           uint32_t idesc, uint32_t en) {
    asm volatile(
        "{\n\t.reg .pred p;\n\tsetp.ne.u32 p, %4, 0;\n\t"
        "tcgen05.mma.cta_group::1.kind::f16 [%0], %1, %2, %3, {%5, %5, %5, %5}, p;\n\t}"
        :: "r"(d), "l"(ad), "l"(bd), "r"(idesc), "r"(en), "r"(0u) : "memory");
}
__device__ __forceinline__ void tc_commit(uint32_t mbar) {
    asm volatile(
        "tcgen05.commit.cta_group::1.mbarrier::arrive::one.shared::cluster.b64 [%0];"
        :: "r"(mbar) : "memory");
}
#define TC_FENCE_AFTER()  asm volatile("tcgen05.fence::after_thread_sync;" ::: "memory")
#define TC_WAIT_LD()      asm volatile("tcgen05.wait::ld.sync.aligned;" ::: "memory")
#define FENCE_ASYNC()     asm volatile("fence.proxy.async.shared::cta;" ::: "memory")
#define TCGEN05_LD_32X32B_X32(r, tmem_addr) \
    asm volatile( \
        "tcgen05.ld.sync.aligned.32x32b.x32.b32 " \
        "{%0, %1, %2, %3, %4, %5, %6, %7, " \
        " %8, %9, %10, %11, %12, %13, %14, %15, " \
        " %16, %17, %18, %19, %20, %21, %22, %23, " \
        " %24, %25, %26, %27, %28, %29, %30, %31}, [%32];" \
        : "=r"((r)[0]),  "=r"((r)[1]),  "=r"((r)[2]),  "=r"((r)[3]), \
          "=r"((r)[4]),  "=r"((r)[5]),  "=r"((r)[6]),  "=r"((r)[7]), \
          "=r"((r)[8]),  "=r"((r)[9]),  "=r"((r)[10]), "=r"((r)[11]), \
          "=r"((r)[12]), "=r"((r)[13]), "=r"((r)[14]), "=r"((r)[15]), \
          "=r"((r)[16]), "=r"((r)[17]), "=r"((r)[18]), "=r"((r)[19]), \
          "=r"((r)[20]), "=r"((r)[21]), "=r"((r)[22]), "=r"((r)[23]), \
          "=r"((r)[24]), "=r"((r)[25]), "=r"((r)[26]), "=r"((r)[27]), \
          "=r"((r)[28]), "=r"((r)[29]), "=r"((r)[30]), "=r"((r)[31]) \
        : "r"(tmem_addr))
#endif // HAS_TCGEN05

#define SWZ(o)   ((o) ^ (((o) >> 3) & 0x70))
#define SWZ64(o) ((o) ^ (((o) >> 3) & 0x30))
#define SMEM_DESC_BASE   ((uint64_t(2) << 61) | (uint64_t(1) << 46) | (uint64_t(64) << 32) | (uint64_t(1) << 16))
#define MK_DESC(addr)   (SMEM_DESC_BASE | ((uint64_t)((addr) >> 4) & 0x3FFF))
// SW64 (64B rows): layout=4, version=1, SBO=32 (8 rows x 64B), LBO=1
#define SMEM_DESC_BASE64 ((uint64_t(4) << 61) | (uint64_t(1) << 46) | (uint64_t(32) << 32) | (uint64_t(1) << 16))
#define MK_D64(addr)    (SMEM_DESC_BASE64 | ((uint64_t)((addr) >> 4) & 0x3FFF))
#define MMA_IDESC   0x8200490u
#define IDESC_PV    0x8100490u

// ---------------- weight convert+transpose: W[K][N] -> o[N][2K] [hi|lo] ------
__device__ __forceinline__ void conv_w_body(const float* __restrict__ W,
                                            __nv_bfloat16* __restrict__ o, int K, int N) {
    __shared__ float t[32][33];
    int n0 = blockIdx.x * 32, k0 = blockIdx.y * 32;
    if (n0 >= N || k0 >= K) return;
    int tx = threadIdx.x, ty = threadIdx.y; // 32 x 8
    #pragma unroll
    for (int i = 0; i < 4; i++)
        t[ty + 8 * i][tx] = W[(size_t)(k0 + ty + 8 * i) * N + n0 + tx];
    __syncthreads();
    size_t K2 = 2 * (size_t)K;
    #pragma unroll
    for (int i = 0; i < 4; i++) {
        int nn = ty + 8 * i, kk = tx;
        float x = t[kk][nn];
        __nv_bfloat16 hi, lo; split_bf16(x, hi, lo);
        size_t base = (size_t)(n0 + nn) * K2 + (size_t)(k0 + kk);
        o[base] = hi; o[base + K] = lo;
    }
}
__global__ void conv_w4_kernel(const float* __restrict__ w0, const float* __restrict__ w1,
                               const float* __restrict__ w2, const float* __restrict__ w3,
                               __nv_bfloat16* o0, __nv_bfloat16* o1,
                               __nv_bfloat16* o2, __nv_bfloat16* o3) {
    const float* W = (blockIdx.z == 0) ? w0 : (blockIdx.z == 1) ? w1 : (blockIdx.z == 2) ? w2 : w3;
    __nv_bfloat16* O = (blockIdx.z == 0) ? o0 : (blockIdx.z == 1) ? o1 : (blockIdx.z == 2) ? o2 : o3;
    conv_w_body(W, O, TB_D, TB_D);
}
__global__ void conv_win_kernel(const float* __restrict__ w_in, __nv_bfloat16* win3) {
    conv_w_body(w_in, win3, TB_D, TB_F);
}
__global__ void conv_wout_kernel(const float* __restrict__ w_out, __nv_bfloat16* wout3) {
    conv_w_body(w_out, wout3, TB_F, TB_D);
}

// ---------------- srmsnorm -> split-bf16 [hi(D)|lo(D)] -----------------------
__global__ void srmsnorm3_kernel(const float* __restrict__ x, __nv_bfloat16* __restrict__ y) {
    int row = blockIdx.x;
    int tid = threadIdx.x;
    const float* xr = x + (size_t)row * TB_D;
    float4 v = *(const float4*)(xr + tid * 4);
    float ss = v.x*v.x + v.y*v.y + v.z*v.z + v.w*v.w;
    #pragma unroll
    for (int o = 16; o; o >>= 1) ss += __shfl_xor_sync(0xffffffffu, ss, o);
    __shared__ float wred[8];
    __shared__ float s_scale;
    if ((tid & 31) == 0) wred[tid >> 5] = ss;
    __syncthreads();
    if (tid == 0) {
        float tot = 0.f;
        #pragma unroll
        for (int i = 0; i < 8; i++) tot += wred[i];
        s_scale = 32.0f / fmaxf(sqrtf(tot), 1e-12f);
    }
    __syncthreads();
    float sc = s_scale;
    float vals[4] = {v.x * sc, v.y * sc, v.z * sc, v.w * sc};
    __nv_bfloat16 hi[4], lo[4];
    #pragma unroll
    for (int j = 0; j < 4; j++) split_bf16(vals[j], hi[j], lo[j]);
    uint2 h2 = pack4bf(hi[0], hi[1], hi[2], hi[3]);
    uint2 l2 = pack4bf(lo[0], lo[1], lo[2], lo[3]);
    size_t base = (size_t)row * TB_D2 + tid * 4;
    *(uint2*)(y + base)        = h2;
    *(uint2*)(y + base + TB_D) = l2;
}

// ---------------- R13 tcgen05 GEMM (128x256 tile; O-proj & FFN2) -------------
#define ST_A 32768
#define ST_B 65536
#define STAGE2 (ST_A + ST_B)            // 96KB
#define GEMM_SMEM (2 * STAGE2 + 1024)   // 193KB

template<int EPI>
__global__ __launch_bounds__(256, 1) void tc_gemm(
    const __nv_bfloat16* __restrict__ A2, const __nv_bfloat16* __restrict__ B2,
    const float* __restrict__ res, void* __restrict__ Cout, int N, int K)
{
    int K2 = 2 * K;
    int m0 = blockIdx.y * 128, n0 = blockIdx.x * 256;
#if HAS_TCGEN05
    extern __shared__ char dsm_raw[];
    __shared__ uint32_t s_tmem;
    __shared__ __align__(8) uint64_t s_bars[4]; // full[2], empty[2]
    char* dsp = (char*)(((uintptr_t)dsm_raw + 1023) & ~(uintptr_t)1023);
    uint32_t dsm = smem_u32(dsp);
    int tid = threadIdx.x, wid = tid >> 5, lane = tid & 31;

    if (wid == 0) {
        asm volatile("tcgen05.alloc.cta_group::1.sync.aligned.shared::cta.b32 [%0], %1;"
                     :: "r"(smem_u32((void*)&s_tmem)), "r"(256u) : "memory");
    }
    if (tid == 0) {
        #pragma unroll
        for (int s = 0; s < 2; s++) {
            mbar_init(smem_u32(&s_bars[s]), 128);
            mbar_init(smem_u32(&s_bars[2 + s]), 1);
        }
    }
    __syncthreads();
    uint32_t tmem = s_tmem;

    const __nv_bfloat16* Ab = A2 + (size_t)m0 * K2;
    const __nv_bfloat16* Bb = B2 + (size_t)n0 * K2;
    int nch = K >> 6;    // even

    if (wid < 4) {
        for (int c = 0; c < nch; c++) {
            int s = c & 1;
            uint32_t sb = dsm + s * STAGE2;
            if (c >= 2)
                mbar_wait(smem_u32(&s_bars[2 + s]), ((c >> 1) - 1) & 1);
            const __nv_bfloat16* ga = Ab + (c << 6);
            const __nv_bfloat16* gb = Bb + (c << 6);
            #pragma unroll
            for (int i = 0; i < 8; i++) {
                int u = tid + (i << 7);
                int r = u >> 3, q = u & 7;
                cp_async16(sb + SWZ(r * 128 + q * 16), ga + (size_t)r * K2 + q * 8);
            }
            #pragma unroll
            for (int i = 0; i < 8; i++) {
                int u = tid + (i << 7);
                int r = u >> 3, q = u & 7;
                cp_async16(sb + 16384 + SWZ(r * 128 + q * 16), ga + (size_t)r * K2 + K + q * 8);
            }
            #pragma unroll
            for (int i = 0; i < 16; i++) {
                int u = tid + (i << 7);
                int r = u >> 3, q = u & 7;
                cp_async16(sb + 32768 + SWZ(r * 128 + q * 16), gb + (size_t)r * K2 + q * 8);
            }
            #pragma unroll
            for (int i = 0; i < 16; i++) {
                int u = tid + (i << 7);
                int r = u >> 3, q = u & 7;
                cp_async16(sb + 65536 + SWZ(r * 128 + q * 16), gb + (size_t)r * K2 + K + q * 8);
            }
            cp_async_arrive(smem_u32(&s_bars[s]));
        }
        uint32_t pe = ((uint32_t)(nch >> 1) - 1u) & 1u;
        #pragma unroll
        for (int s = 0; s < 2; s++)
            mbar_wait(smem_u32(&s_bars[2 + s]), pe);
    } else if (wid == 7) {
        for (int c = 0; c < nch; c++) {
            int s = c & 1;
            uint32_t sb = dsm + s * STAGE2;
            mbar_wait(smem_u32(&s_bars[s]), (c >> 1) & 1);
            if (elect_one()) {
                uint64_t ah  = MK_DESC(sb);
                uint64_t al  = MK_DESC(sb + 16384);
                uint64_t bh0 = MK_DESC(sb + 32768);
                uint64_t bh1 = MK_DESC(sb + 49152);
                uint64_t bl0 = MK_DESC(sb + 65536);
                uint64_t bl1 = MK_DESC(sb + 81920);
                #pragma unroll
                for (int seg = 0; seg < 3; seg++) {
                    uint64_t a  = (seg == 1) ? al : ah;
                    uint64_t b0 = (seg == 2) ? bl0 : bh0;
                    uint64_t b1 = (seg == 2) ? bl1 : bh1;
                    #pragma unroll
                    for (int k = 0; k < 4; k++) {
                        uint32_t en = (c | seg | k) ? 1u : 0u;
                        mma_f16_ss(tmem,       a + 2*k, b0 + 2*k, MMA_IDESC, en);
                        mma_f16_ss(tmem + 128, a + 2*k, b1 + 2*k, MMA_IDESC, en);
                    }
                }
                tc_commit(smem_u32(&s_bars[2 + s]));
            }
        }
    }
    __syncthreads();
    TC_FENCE_AFTER();

    int sub = wid & 3, half = wid >> 2;
    int mrow = m0 + sub * 32 + lane;
    for (int cb = 0; cb < 128; cb += 32) {
        uint32_t dr[32];
        TCGEN05_LD_32X32B_X32(dr, tmem + half * 128 + cb);
        TC_WAIT_LD();
        int n = n0 + half * 128 + cb;
        float* C = (float*)Cout;
        size_t base = (size_t)mrow * N + n;
        #pragma unroll
        for (int j = 0; j < 32; j += 4) {
            float4 v = make_float4(__uint_as_float(dr[j]),   __uint_as_float(dr[j+1]),
                                   __uint_as_float(dr[j+2]), __uint_as_float(dr[j+3]));
            if (EPI == 1) {
                float4 r4 = *(const float4*)(res + base + j);
                v.x += r4.x; v.y += r4.y; v.z += r4.z; v.w += r4.w;
            }
            *(float4*)(C + base + j) = v;
        }
    }
    __syncthreads();
    if (wid == 0) {
        asm volatile("tcgen05.relinquish_alloc_permit.cta_group::1.sync.aligned;");
        asm volatile("tcgen05.dealloc.cta_group::1.sync.aligned.b32 %0, %1;"
                     :: "r"(tmem), "r"(256u));
    }
#else
    int tid = threadIdx.x;
    int n_c = n0 + tid;
    for (int m = 0; m < 128; m++) {
        int mrow = m0 + m;
        const __nv_bfloat16* ar = A2 + (size_t)mrow * K2;
        const __nv_bfloat16* br = B2 + (size_t)n_c * K2;
        float acc = 0.f;
        for (int k = 0; k < K; k++) {
            float ah = __bfloat162float(ar[k]), al = __bfloat162float(ar[K + k]);
            float bh = __bfloat162float(br[k]), bl = __bfloat162float(br[K + k]);
            acc += ah * bh + al * bh + ah * bl;
        }
        float* C = (float*)Cout;
        size_t base = (size_t)mrow * N;
        if (EPI == 1) acc += res[base + n_c];
        C[base + n_c] = acc;
    }
#endif
}

// ---------------- 256x256-tile tcgen05 GEMM (SW64, K32 chunks, 3 stages) ------
// epi: 2 = gelu->[hi|lo], 3 = Q split, 4 = K split, 5 = V transposed split
#define ST64 65536
#define G256_SMEM (3 * ST64 + 1024)   // 193KB

__global__ __launch_bounds__(256, 1) void tc_gemm256(
    const __nv_bfloat16* __restrict__ A2,
    const __nv_bfloat16* __restrict__ b0, const __nv_bfloat16* __restrict__ b1,
    const __nv_bfloat16* __restrict__ b2,
    void* __restrict__ c0, void* __restrict__ c1, void* __restrict__ c2,
    int N, int K, int epi_base, int nmat)
{
    int K2 = 2 * K;
    int m0 = blockIdx.y * 256, n0 = blockIdx.x * 256;
    int mat = (nmat == 3) ? (int)blockIdx.z : 0;
    const __nv_bfloat16* B2 = (mat == 0) ? b0 : (mat == 1) ? b1 : b2;
    void* Cout = (mat == 0) ? c0 : (mat == 1) ? c1 : c2;
    int epi = (nmat == 3) ? (3 + mat) : epi_base;
#if HAS_TCGEN05
    extern __shared__ char dsm_raw[];
    __shared__ uint32_t s_tmem;
    __shared__ __align__(8) uint64_t s_bars[6]; // full[3], empty[3]
    char* dsp = (char*)(((uintptr_t)dsm_raw + 1023) & ~(uintptr_t)1023);
    uint32_t dsm = smem_u32(dsp);
    int tid = threadIdx.x, wid = tid >> 5, lane = tid & 31;

    if (wid == 0) {
        asm volatile("tcgen05.alloc.cta_group::1.sync.aligned.shared::cta.b32 [%0], %1;"
                     :: "r"(smem_u32((void*)&s_tmem)), "r"(512u) : "memory");
    }
    if (tid == 0) {
        #pragma unroll
        for (int s = 0; s < 3; s++) {
            mbar_init(smem_u32(&s_bars[s]), 128);      // full
            mbar_init(smem_u32(&s_bars[3 + s]), 1);    // empty (commit)
        }
    }
    __syncthreads();
    uint32_t tmem = s_tmem;

    const __nv_bfloat16* Ab = A2 + (size_t)m0 * K2;
    const __nv_bfloat16* Bb = B2 + (size_t)n0 * K2;
    int nch = K >> 5;    // K32 chunks (32 for K=1024)

    if (wid < 4) {
        // loaders: 4 planes x 16KB per stage; SW64 (64B rows)
        uint32_t cE[3] = {0, 0, 0};
        for (int c = 0; c < nch; c++) {
            int s = c % 3;
            uint32_t sb = dsm + s * ST64;
            if (c >= 3) { mbar_wait(smem_u32(&s_bars[3 + s]), cE[s] & 1); cE[s]++; }
            const __nv_bfloat16* ga = Ab + (c << 5);
            const __nv_bfloat16* gb = Bb + (c << 5);
            #pragma unroll
            for (int i = 0; i < 8; i++) {              // A hi: 256 x 64B
                int u = tid + (i << 7);
                int r = u >> 2, q = u & 3;
                cp_async16(sb + SWZ64(r * 64 + q * 16), ga + (size_t)r * K2 + q * 8);
            }
            #pragma unroll
            for (int i = 0; i < 8; i++) {              // A lo
                int u = tid + (i << 7);
                int r = u >> 2, q = u & 3;
                cp_async16(sb + 16384 + SWZ64(r * 64 + q * 16), ga + (size_t)r * K2 + K + q * 8);
            }
            #pragma unroll
            for (int i = 0; i < 8; i++) {              // B hi: 256 x 64B
                int u = tid + (i << 7);
                int r = u >> 2, q = u & 3;
                cp_async16(sb + 32768 + SWZ64(r * 64 + q * 16), gb + (size_t)r * K2 + q * 8);
            }
            #pragma unroll
            for (int i = 0; i < 8; i++) {              // B lo
                int u = tid + (i << 7);
                int r = u >> 2, q = u & 3;
                cp_async16(sb + 49152 + SWZ64(r * 64 + q * 16), gb + (size_t)r * K2 + K + q * 8);
            }
            cp_async_arrive(smem_u32(&s_bars[s]));
        }
        // drain: consume the final commit of each stage -> ALL MMAs complete
        #pragma unroll
        for (int s = 0; s < 3; s++)
            mbar_wait(smem_u32(&s_bars[3 + s]), cE[s] & 1);
    } else if (wid == 7) {
        uint32_t cF[3] = {0, 0, 0};
        for (int c = 0; c < nch; c++) {
            int s = c % 3;
            uint32_t sb = dsm + s * ST64;
            mbar_wait(smem_u32(&s_bars[s]), cF[s] & 1); cF[s]++;
            if (elect_one()) {
                uint64_t ah = MK_D64(sb);
                uint64_t al = MK_D64(sb + 16384);
                uint64_t bh = MK_D64(sb + 32768);
                uint64_t bl = MK_D64(sb + 49152);
                #pragma unroll
                for (int seg = 0; seg < 3; seg++) {
                    uint64_t a = (seg == 1) ? al : ah;
                    uint64_t b = (seg == 2) ? bl : bh;
                    #pragma unroll
                    for (int ks = 0; ks < 2; ks++) {
                        uint32_t en = (c | seg | ks) ? 1u : 0u;
                        #pragma unroll
                        for (int mh = 0; mh < 2; mh++)
                            #pragma unroll
                            for (int nh = 0; nh < 2; nh++)
                                mma_f16_ss(tmem + mh * 256 + nh * 128,
                                           a + mh * 512 + ks * 2,
                                           b + nh * 512 + ks * 2,
                                           MMA_IDESC, en);
                    }
                }
                tc_commit(smem_u32(&s_bars[3 + s]));   // ONE commit per chunk
            }
        }
    }
    __syncthreads();
    TC_FENCE_AFTER();

    // epilogue: warp w -> Mhalf = w>>2, subpartition = w&3; 256 cols each
    int sub = wid & 3, mh = wid >> 2;
    int mrow = m0 + mh * 128 + sub * 32 + lane;
    for (int cb = 0; cb < 256; cb += 32) {
        uint32_t dr[32];
        TCGEN05_LD_32X32B_X32(dr, tmem + mh * 256 + cb);
        TC_WAIT_LD();
        int n = n0 + cb;
        if (epi == 2) {
            __nv_bfloat16* C = (__nv_bfloat16*)Cout;
            size_t rb = (size_t)mrow * (2 * (size_t)N);
            __nv_bfloat16 hiA[32], loA[32];
            #pragma unroll
            for (int j = 0; j < 32; j++) {
                float f = gelu_tanh(__uint_as_float(dr[j]));
                split_bf16(f, hiA[j], loA[j]);
            }
            uint4* ph = (uint4*)(C + rb + n);
            uint4* pl = (uint4*)(C + rb + (size_t)N + n);
            #pragma unroll
            for (int t2 = 0; t2 < 4; t2++) {
                ph[t2] = ((uint4*)hiA)[t2];
                pl[t2] = ((uint4*)loA)[t2];
            }
        } else if (epi == 3 || epi == 4) {
            __nv_bfloat16* C = (__nv_bfloat16*)Cout;
            int bb = mrow >> 11, tl = mrow & 2047;
            int head = n >> 6, d0 = n & 63;
            __nv_bfloat16 hiA[32], loA[32];
            #pragma unroll
            for (int j = 0; j < 32; j++)
                split_bf16(__uint_as_float(dr[j]), hiA[j], loA[j]);
            __nv_bfloat16* dst = C + (((size_t)(bb * 16 + head)) * 2048 + tl) * 128;
            uint4* ph = (uint4*)(dst + d0);
            uint4* pl = (uint4*)(dst + 64 + d0);
            #pragma unroll
            for (int t2 = 0; t2 < 4; t2++) {
                ph[t2] = ((uint4*)hiA)[t2];
                pl[t2] = ((uint4*)loA)[t2];
            }
        } else { // epi == 5: V transposed
            __nv_bfloat16* C = (__nv_bfloat16*)Cout;
            int bb = mrow >> 11;
            int head = n >> 6, d0 = n & 63;
            int tl0 = (m0 & 2047) + mh * 128 + sub * 32;
            __nv_bfloat16 hiA[32], loA[32];
            #pragma unroll
            for (int j = 0; j < 32; j++)
                split_bf16(__uint_as_float(dr[j]), hiA[j], loA[j]);
            // scratch in dead stage smem (post-drain)
            uint16_t* sc  = (uint16_t*)(dsp + (size_t)wid * 4352);
            uint16_t* scl = sc + 1088;
            #pragma unroll
            for (int j = 0; j < 32; j++) {
                sc [lane * 34 + j] = __bfloat16_as_ushort(hiA[j]);
                scl[lane * 34 + j] = __bfloat16_as_ushort(loA[j]);
            }
            __syncwarp();
            uint32_t wh[16], wl[16];
            #pragma unroll
            for (int g = 0; g < 16; g++) {
                wh[g] = (uint32_t)sc [(2*g) * 34 + lane] | ((uint32_t)sc [(2*g+1) * 34 + lane] << 16);
                wl[g] = (uint32_t)scl[(2*g) * 34 + lane] | ((uint32_t)scl[(2*g+1) * 34 + lane] << 16);
            }
            size_t base_hb = (size_t)(bb * 16 + head) * 262144;
            __nv_bfloat16* dh = C + base_hb + (size_t)(d0 + lane) * 2048 + tl0;
            __nv_bfloat16* dl = C + base_hb + (size_t)(64 + d0 + lane) * 2048 + tl0;
            #pragma unroll
            for (int g = 0; g < 4; g++) {
                ((uint4*)dh)[g] = ((uint4*)wh)[g];
                ((uint4*)dl)[g] = ((uint4*)wl)[g];
            }
            __syncwarp();
        }
    }
    __syncthreads();
    if (wid == 0) {
        asm volatile("tcgen05.relinquish_alloc_permit.cta_group::1.sync.aligned;");
        asm volatile("tcgen05.dealloc.cta_group::1.sync.aligned.b32 %0, %1;"
                     :: "r"(tmem), "r"(512u));
    }
#else
    // SIMT fallback
    int tid = threadIdx.x;
    int n_c = n0 + tid;
    for (int m = 0; m < 256; m++) {
        int mrow = m0 + m;
        const __nv_bfloat16* ar = A2 + (size_t)mrow * K2;
        const __nv_bfloat16* br = B2 + (size_t)n_c * K2;
        float acc = 0.f;
        for (int k = 0; k < K; k++) {
            float ah = __bfloat162float(ar[k]), al = __bfloat162float(ar[K + k]);
            float bh = __bfloat162float(br[k]), bl = __bfloat162float(br[K + k]);
            acc += ah * bh + al * bh + ah * bl;
        }
        if (epi == 2) {
            __nv_bfloat16* C = (__nv_bfloat16*)Cout;
            size_t base = (size_t)mrow * (2 * (size_t)N);
            float f = gelu_tanh(acc);
            __nv_bfloat16 hi, lo; split_bf16(f, hi, lo);
            C[base + n_c] = hi; C[base + N + n_c] = lo;
        } else if (epi == 3 || epi == 4) {
            __nv_bfloat16* C = (__nv_bfloat16*)Cout;
            int bb = mrow >> 11, tl = mrow & 2047;
            int head = n_c >> 6, d = n_c & 63;
            __nv_bfloat16 hi, lo; split_bf16(acc, hi, lo);
            size_t base = (((size_t)(bb * 16 + head)) * 2048 + tl) * 128;
            C[base + d] = hi; C[base + 64 + d] = lo;
        } else {
            __nv_bfloat16* C = (__nv_bfloat16*)Cout;
            int bb = mrow >> 11, tl = mrow & 2047;
            int head = n_c >> 6, d = n_c & 63;
            __nv_bfloat16 hi, lo; split_bf16(acc, hi, lo);
            size_t base = (size_t)(bb * 16 + head) * 262144;
            C[base + (size_t)d * 2048 + tl] = hi;
            C[base + (size_t)(64 + d) * 2048 + tl] = lo;
        }
    }
#endif
}

// ---------------- tcgen05 causal flash attention (unchanged from R13 win) -----
#define ATT_DSMEM (192 * 1024 + 1024)

__global__ __launch_bounds__(256, 1) void tc_attn(
    const __nv_bfloat16* __restrict__ q3, const __nv_bfloat16* __restrict__ k3,
    const __nv_bfloat16* __restrict__ vt3, __nv_bfloat16* __restrict__ att3)
{
    int qtile = 15 - (int)blockIdx.x;          // heavy tiles first
    int h = blockIdx.y, b = blockIdx.z;
    int ntiles = qtile + 1;
    int q0 = qtile * 128;
    size_t hb = (size_t)b * 16 + h;
    const __nv_bfloat16* qh = q3 + hb * (size_t)2048 * 128;
    const __nv_bfloat16* kh = k3 + hb * (size_t)2048 * 128;
    const __nv_bfloat16* vh = vt3 + hb * (size_t)262144;
#if HAS_TCGEN05
    extern __shared__ char dsm_raw[];
    __shared__ uint32_t s_tmem;
    __shared__ __align__(8) uint64_t bars[7]; // bK0 bK1 bV bP bO bSK0 bSK1
    char* dsmp = (char*)(((uintptr_t)dsm_raw + 1023) & ~(uintptr_t)1023);
    uint32_t dsm = smem_u32(dsmp);
    uint32_t Q0c = dsm, Q1c = dsm + 16384;
    uint32_t Kst = dsm + 32768;
    uint32_t Vt  = dsm + 98304;
    uint32_t Pb  = dsm + 131072;
    uint32_t bK[2]  = { smem_u32(&bars[0]), smem_u32(&bars[1]) };
    uint32_t bV = smem_u32(&bars[2]), bP = smem_u32(&bars[3]);
    uint32_t bO = smem_u32(&bars[4]);
    uint32_t bSK[2] = { smem_u32(&bars[5]), smem_u32(&bars[6]) };
    int tid = threadIdx.x, wid = tid >> 5, lane = tid & 31;

    if (wid == 0) {
        asm volatile("tcgen05.alloc.cta_group::1.sync.aligned.shared::cta.b32 [%0], %1;"
                     :: "r"(smem_u32((void*)&s_tmem)), "r"(256u) : "memory");
    }
    if (tid == 0) {
        mbar_init(bK[0], 64); mbar_init(bK[1], 64);
        mbar_init(bV, 32); mbar_init(bP, 128); mbar_init(bO, 1);
        mbar_init(bSK[0], 1); mbar_init(bSK[1], 1);
    }
    __syncthreads();
    uint32_t tmem = s_tmem;

    if (wid >= 4) {
        int t4 = tid - 128;
        #pragma unroll
        for (int i = 0; i < 8; i++) {
            int u = t4 + 128 * i, r = u >> 3, q = u & 7;
            cp_async16(Q0c + SWZ(r * 128 + q * 16), qh + (size_t)(q0 + r) * 128 + q * 8);
        }
        #pragma unroll
        for (int i = 0; i < 8; i++) {
            int u = t4 + 128 * i, r = u >> 3, q = u & 7;
            cp_async16(Q1c + SWZ(r * 128 + q * 16), qh + (size_t)(q0 + r) * 128 + 64 + q * 8);
        }
        asm volatile("cp.async.wait_all;" ::: "memory");
    }
    __syncthreads();

    if (wid == 4 || wid == 5) {
        int t2 = tid - 128;
        for (int t = 0; t < ntiles; t++) {
            if (t >= 2) mbar_wait(bSK[t & 1], ((t >> 1) - 1) & 1);
            uint32_t Ks = Kst + (t & 1) * 32768;
            int k0 = t * 128;
            #pragma unroll
            for (int i = 0; i < 16; i++) {
                int u = t2 + 64 * i, r = u >> 3, q = u & 7;
                cp_async16(Ks + SWZ(r * 128 + q * 16), kh + (size_t)(k0 + r) * 128 + q * 8);
            }
            #pragma unroll
            for (int i = 0; i < 16; i++) {
                int u = t2 + 64 * i, r = u >> 3, q = u & 7;
                cp_async16(Ks + 16384 + SWZ(r * 128 + q * 16), kh + (size_t)(k0 + r) * 128 + 64 + q * 8);
            }
            cp_async_arrive(bK[t & 1]);
        }
    } else if (wid == 6) {
        int t3 = tid - 192;
        for (int t = 0; t < ntiles; t++) {
            if (t >= 1) mbar_wait(bO, (t - 1) & 1);
            int k0 = t * 128;
            #pragma unroll
            for (int p = 0; p < 2; p++)
                #pragma unroll
                for (int cc = 0; cc < 2; cc++) {
                    uint32_t cb = Vt + (p * 2 + cc) * 8192;
                    #pragma unroll
                    for (int i = 0; i < 16; i++) {
                        int u = t3 + 32 * i, r = u >> 3, q = u & 7;
                        cp_async16(cb + SWZ(r * 128 + q * 16),
                                   vh + (size_t)(p * 64 + r) * 2048 + k0 + cc * 64 + q * 8);
                    }
                }
            cp_async_arrive(bV);
        }
    } else if (wid == 7) {
        for (int t = 0; t < ntiles; t++) {
            mbar_wait(bK[t & 1], (t >> 1) & 1);
            if (elect_one()) {
                uint32_t Ks = Kst + (t & 1) * 32768;
                uint64_t qd[3] = { MK_DESC(Q0c), MK_DESC(Q1c), MK_DESC(Q0c) };
                uint64_t kd[3] = { MK_DESC(Ks), MK_DESC(Ks), MK_DESC(Ks + 16384) };
                #pragma unroll
                for (int seg = 0; seg < 3; seg++)
                    #pragma unroll
                    for (int s = 0; s < 4; s++)
                        mma_f16_ss(tmem, qd[seg] + 2 * s, kd[seg] + 2 * s,
                                   MMA_IDESC, (seg | s) ? 1u : 0u);
                tc_commit(bSK[t & 1]);
            }
            mbar_wait(bV, t & 1);
            mbar_wait(bP, t & 1);
            if (elect_one()) {
                uint64_t pa[3][2] = {
                    { MK_DESC(Pb),         MK_DESC(Pb + 16384) },
                    { MK_DESC(Pb + 32768), MK_DESC(Pb + 49152) },
                    { MK_DESC(Pb),         MK_DESC(Pb + 16384) } };
                const int vpart[3] = { 0, 0, 1 };
                #pragma unroll
                for (int seg = 0; seg < 3; seg++)
                    #pragma unroll
                    for (int s = 0; s < 8; s++) {
                        int cc = s >> 2;
                        mma_f16_ss(tmem + 128,
                                   pa[seg][cc] + 2 * (s & 3),
                                   MK_DESC(Vt + (vpart[seg] * 2 + cc) * 8192) + 2 * (s & 3),
                                   IDESC_PV, (seg | s) ? 1u : 0u);
                    }
                tc_commit(bO);
            }
        }
    } else {
        int rloc = wid * 32 + lane;
        int rg = q0 + rloc;
        float m = -1e30f, l = 0.f, alpha_prev = 0.f;
        float O[64];
        #pragma unroll
        for (int j = 0; j < 64; j++) O[j] = 0.f;

        for (int t = 0; t < ntiles; t++) {
            mbar_wait(bSK[t & 1], (t >> 1) & 1);
            TC_FENCE_AFTER();
            int k0 = t * 128;
            int lim = rg - k0;
            float s[128];
            float mt = -1e30f;
            #pragma unroll
            for (int cb = 0; cb < 4; cb++) {
                uint32_t dr[32];
                TCGEN05_LD_32X32B_X32(dr, tmem + cb * 32);
                TC_WAIT_LD();
                #pragma unroll
                for (int j = 0; j < 32; j++) {
                    int c = cb * 32 + j;
                    float v = (c <= lim) ? __uint_as_float(dr[j]) * 0.125f : -1e30f;
                    s[c] = v;
                    mt = fmaxf(mt, v);
                }
            }
            float mn = fmaxf(m, mt);
            float al = __expf(m - mn);
            if (t > 0) {
                mbar_wait(bO, (t - 1) & 1);
                TC_FENCE_AFTER();
                uint32_t du[32];
                TCGEN05_LD_32X32B_X32(du, tmem + 128);
                TC_WAIT_LD();
                #pragma unroll
                for (int j = 0; j < 32; j++)
                    O[j] = O[j] * alpha_prev + __uint_as_float(du[j]);
                TCGEN05_LD_32X32B_X32(du, tmem + 160);
                TC_WAIT_LD();
                #pragma unroll
                for (int j = 0; j < 32; j++)
                    O[32 + j] = O[32 + j] * alpha_prev + __uint_as_float(du[j]);
            }
            float ps = 0.f;
            #pragma unroll
            for (int c = 0; c < 128; c += 4) {
                float p0 = __expf(s[c]     - mn);
                float p1 = __expf(s[c + 1] - mn);
                float p2 = __expf(s[c + 2] - mn);
                float p3 = __expf(s[c + 3] - mn);
                ps += (p0 + p1) + (p2 + p3);
                __nv_bfloat16 h0,l0,h1,l1,h2,l2,h3,l3;
                split_bf16(p0, h0, l0); split_bf16(p1, h1, l1);
                split_bf16(p2, h2, l2); split_bf16(p3, h3, l3);
                uint2 hv = pack4bf(h0, h1, h2, h3);
                uint2 lv = pack4bf(l0, l1, l2, l3);
                int subo = (c >> 6) * 16384;
                uint32_t so = SWZ(rloc * 128 + (c & 63) * 2);
                *(uint2*)(dsmp + 131072 + subo + so) = hv;   // Phi
                *(uint2*)(dsmp + 163840 + subo + so) = lv;   // Plo
            }
            l = l * al + ps;
            alpha_prev = al;
            m = mn;
            FENCE_ASYNC();
            mbar_arrive(bP);
        }
        mbar_wait(bO, (ntiles - 1) & 1);
        TC_FENCE_AFTER();
        {
            uint32_t du[32];
            TCGEN05_LD_32X32B_X32(du, tmem + 128);
            TC_WAIT_LD();
            #pragma unroll
            for (int j = 0; j < 32; j++)
                O[j] = O[j] * alpha_prev + __uint_as_float(du[j]);
            TCGEN05_LD_32X32B_X32(du, tmem + 160);
            TC_WAIT_LD();
            #pragma unroll
            for (int j = 0; j < 32; j++)
                O[32 + j] = O[32 + j] * alpha_prev + __uint_as_float(du[j]);
        }
        float inv = 1.0f / l;
        __nv_bfloat16 hi[64], lo[64];
        #pragma unroll
        for (int j = 0; j < 64; j++) split_bf16(O[j] * inv, hi[j], lo[j]);
        size_t rb = ((size_t)b * 2048 + rg) * TB_D2 + h * 64;
        uint4* ph = (uint4*)(att3 + rb);
        uint4* pl = (uint4*)(att3 + rb + TB_D);
        #pragma unroll
        for (int i = 0; i < 8; i++) {
            ph[i] = ((uint4*)hi)[i];
            pl[i] = ((uint4*)lo)[i];
        }
    }
    __syncthreads();
    if (wid == 0) {
        asm volatile("tcgen05.relinquish_alloc_permit.cta_group::1.sync.aligned;");
        asm volatile("tcgen05.dealloc.cta_group::1.sync.aligned.b32 %0, %1;"
                     :: "r"(tmem), "r"(256u));
    }
#else
    int tid = threadIdx.x;
    if (tid < 128) {
        int rg = q0 + tid;
        float q[64];
        #pragma unroll
        for (int d = 0; d < 64; d++)
            q[d] = __bfloat162float(qh[(size_t)rg * 128 + d]) +
                   __bfloat162float(qh[(size_t)rg * 128 + 64 + d]);
        float m = -1e30f;
        for (int k = 0; k <= rg; k++) {
            float s = 0.f;
            for (int d = 0; d < 64; d++)
                s += q[d] * (__bfloat162float(kh[(size_t)k * 128 + d]) +
                             __bfloat162float(kh[(size_t)k * 128 + 64 + d]));
            m = fmaxf(m, s * 0.125f);
        }
        float l = 0.f, O[64];
        for (int d = 0; d < 64; d++) O[d] = 0.f;
        for (int k = 0; k <= rg; k++) {
            float s = 0.f;
            for (int d = 0; d < 64; d++)
                s += q[d] * (__bfloat162float(kh[(size_t)k * 128 + d]) +
                             __bfloat162float(kh[(size_t)k * 128 + 64 + d]));
            float p = expf(s * 0.125f - m);
            l += p;
            for (int d = 0; d < 64; d++)
                O[d] += p * (__bfloat162float(vh[(size_t)d * 2048 + k]) +
                             __bfloat162float(vh[(size_t)(64 + d) * 2048 + k]));
        }
        float inv = 1.0f / l;
        size_t rb = ((size_t)b * 2048 + rg) * TB_D2 + h * 64;
        for (int d = 0; d < 64; d++) {
            __nv_bfloat16 hi, lo; split_bf16(O[d] * inv, hi, lo);
            att3[rb + d] = hi; att3[rb + TB_D + d] = lo;
        }
    }
#endif
}

// ---------------- launch ------------------------------------------------------
extern "C" void kernel_launch(void* const* d_in, const int* in_sizes, int n_in,
                              void* d_out, int out_size) {
    const float* x     = (const float*)d_in[0];
    const float* wq    = (const float*)d_in[1];
    const float* wk    = (const float*)d_in[2];
    const float* wv    = (const float*)d_in[3];
    const float* wo    = (const float*)d_in[4];
    const float* w_in  = (const float*)d_in[5];
    const float* w_out = (const float*)d_in[6];
    float* out = (float*)d_out;
    (void)in_sizes; (void)n_in; (void)out_size;

    __nv_bfloat16 *xn3, *att3, *ff3, *q3, *k3, *vt3;
    __nv_bfloat16 *wq3, *wk3, *wv3, *wo3, *win3, *wout3;
    float *h;
    cudaGetSymbolAddress((void**)&xn3,  g_xn3);
    cudaGetSymbolAddress((void**)&att3, g_att3);
    cudaGetSymbolAddress((void**)&ff3,  g_ff3);
    cudaGetSymbolAddress((void**)&q3,   g_q3);
    cudaGetSymbolAddress((void**)&k3,   g_k3);
    cudaGetSymbolAddress((void**)&vt3,  g_vt3);
    cudaGetSymbolAddress((void**)&h,    g_h);
    cudaGetSymbolAddress((void**)&wq3,  g_wq3);
    cudaGetSymbolAddress((void**)&wk3,  g_wk3);
    cudaGetSymbolAddress((void**)&wv3,  g_wv3);
    cudaGetSymbolAddress((void**)&wo3,  g_wo3);
    cudaGetSymbolAddress((void**)&win3, g_win3);
    cudaGetSymbolAddress((void**)&wout3, g_wout3);

    cudaFuncSetAttribute(tc_attn,    cudaFuncAttributeMaxDynamicSharedMemorySize, ATT_DSMEM);
    cudaFuncSetAttribute(tc_gemm<1>, cudaFuncAttributeMaxDynamicSharedMemorySize, GEMM_SMEM);
    cudaFuncSetAttribute(tc_gemm256, cudaFuncAttributeMaxDynamicSharedMemorySize, G256_SMEM);

    dim3 cwb(32, 8);
    conv_w4_kernel<<<dim3(32, 32, 4), cwb>>>(wq, wk, wv, wo, wq3, wk3, wv3, wo3);   // 1
    conv_win_kernel<<<dim3(128, 32), cwb>>>(w_in, win3);                            // 2
    conv_wout_kernel<<<dim3(32, 128), cwb>>>(w_out, wout3);                         // 3
    srmsnorm3_kernel<<<TB_T, 256>>>(x, xn3);                                        // 4
    // QKV: 256x256 tiles, 16m x 4n x 3 mats
    tc_gemm256<<<dim3(4, 16, 3), 256, G256_SMEM>>>(                                 // 5
        xn3, wq3, wk3, wv3, q3, k3, vt3, TB_D, TB_D, 0, 3);
    tc_attn<<<dim3(16, TB_H, TB_B), 256, ATT_DSMEM>>>(q3, k3, vt3, att3);           // 6
    // O-proj: 128x256 tiles (R13 path)
    tc_gemm<1><<<dim3(4, 32), 256, GEMM_SMEM>>>(att3, wo3, x, h, TB_D, TB_D);       // 7
    srmsnorm3_kernel<<<TB_T, 256>>>(h, xn3);                                        // 8
    // FFN1: 256x256 tiles, 16m x 16n
    tc_gemm256<<<dim3(16, 16), 256, G256_SMEM>>>(                                   // 9
        xn3, win3, win3, win3, ff3, ff3, ff3, TB_F, TB_D, 2, 1);
    // FFN2: 128x256 tiles, K=4096 (R13 path)
    tc_gemm<1><<<dim3(4, 32), 256, GEMM_SMEM>>>(ff3, wout3, h, out, TB_D, TB_F);    // 10
}

// round 17
// speedup vs baseline: 1.1095x; 1.1095x over previous
#include <cuda_runtime.h>
#include <cuda_bf16.h>
#include <math.h>
#include <stdint.h>

// Problem dims (fixed by the reference)
#define TB_B 2
#define TB_S 2048
#define TB_D 1024
#define TB_F 4096
#define TB_H 16
#define TB_HD 64
#define TB_T (TB_B * TB_S)   // 4096 tokens
#define TB_D2 (2 * TB_D)     // 2048 ([hi|lo] split layout)
#define TB_F2 (2 * TB_F)     // 8192

#if defined(__CUDA_ARCH_FEAT_SM103_ALL) || defined(__CUDA_ARCH_FEAT_SM100_ALL)
#define HAS_TCGEN05 1
#else
#define HAS_TCGEN05 0
#endif

// ---------------- scratch ----------------------------------------------------
__device__ __nv_bfloat16 g_xn3 [(size_t)TB_T * TB_D2];
__device__ __nv_bfloat16 g_att3[(size_t)TB_T * TB_D2];
__device__ __nv_bfloat16 g_ff3 [(size_t)TB_T * TB_F2];
__device__ float g_h [(size_t)TB_T * TB_D];
__device__ __nv_bfloat16 g_q3 [(size_t)TB_T * TB_H * 128];
__device__ __nv_bfloat16 g_k3 [(size_t)TB_T * TB_H * 128];
__device__ __nv_bfloat16 g_vt3[(size_t)TB_B * TB_H * 128 * TB_S];
__device__ __nv_bfloat16 g_wq3 [(size_t)TB_D * TB_D2];
__device__ __nv_bfloat16 g_wk3 [(size_t)TB_D * TB_D2];
__device__ __nv_bfloat16 g_wv3 [(size_t)TB_D * TB_D2];
__device__ __nv_bfloat16 g_wo3 [(size_t)TB_D * TB_D2];
__device__ __nv_bfloat16 g_win3[(size_t)TB_F * TB_D2];
__device__ __nv_bfloat16 g_wout3[(size_t)TB_D * TB_F2];

// ---------------- helpers ----------------------------------------------------
__device__ __forceinline__ uint32_t smem_u32(const void* p) {
    uint32_t a;
    asm("{ .reg .u64 t; cvta.to.shared.u64 t, %1; cvt.u32.u64 %0, t; }" : "=r"(a) : "l"(p));
    return a;
}
__device__ __forceinline__ void split_bf16(float x, __nv_bfloat16& hi, __nv_bfloat16& lo) {
    hi = __float2bfloat16(x);
    lo = __float2bfloat16(x - __bfloat162float(hi));
}
// truncation split (P only: x >= 0, residual <= 2^-16 rel) — cheaper by a cvt
__device__ __forceinline__ void split_bf16_trunc(float x, uint16_t& hi, __nv_bfloat16& lo) {
    uint32_t b = __float_as_uint(x);
    hi = (uint16_t)(b >> 16);
    float hf = __uint_as_float(b & 0xFFFF0000u);
    lo = __float2bfloat16(x - hf);
}
__device__ __forceinline__ float gelu_tanh(float v) {
    const float c = 0.79788456080286535588f;
    float t = c * (v + 0.044715f * v * v * v);
    return 0.5f * v * (1.0f + tanhf(t));
}
__device__ __forceinline__ uint2 pack4bf(__nv_bfloat16 a, __nv_bfloat16 b,
                                         __nv_bfloat16 c, __nv_bfloat16 d) {
    uint2 r;
    r.x = (uint32_t)__bfloat16_as_ushort(a) | ((uint32_t)__bfloat16_as_ushort(b) << 16);
    r.y = (uint32_t)__bfloat16_as_ushort(c) | ((uint32_t)__bfloat16_as_ushort(d) << 16);
    return r;
}

#if HAS_TCGEN05
__device__ __forceinline__ uint32_t elect_one() {
    uint32_t p;
    asm volatile("{ .reg .pred p; elect.sync _|p, 0xFFFFFFFF; selp.b32 %0, 1, 0, p; }" : "=r"(p));
    return p;
}
__device__ __forceinline__ void mbar_init(uint32_t a, uint32_t cnt) {
    asm volatile("mbarrier.init.shared.b64 [%0], %1;" :: "r"(a), "r"(cnt) : "memory");
}
__device__ __forceinline__ void mbar_arrive(uint32_t a) {
    asm volatile("mbarrier.arrive.shared.b64 _, [%0];" :: "r"(a) : "memory");
}
__device__ __forceinline__ void mbar_wait(uint32_t a, uint32_t parity) {
    asm volatile(
        "{\n\t.reg .pred P;\n\t"
        "LW%=:\n\t"
        "mbarrier.try_wait.parity.acquire.cta.shared::cta.b64 P, [%0], %1, 0x989680;\n\t"
        "@P bra LD%=;\n\t"
        "bra LW%=;\n\t"
        "LD%=:\n\t}"
        :: "r"(a), "r"(parity) : "memory");
}
__device__ __forceinline__ void cp_async16(uint32_t dst, const void* src) {
    asm volatile("cp.async.cg.shared.global [%0], [%1], 16;" :: "r"(dst), "l"(src) : "memory");
}
__device__ __forceinline__ void cp_async_arrive(uint32_t mbar) {
    asm volatile("cp.async.mbarrier.arrive.noinc.shared::cta.b64 [%0];" :: "r"(mbar) : "memory");
}
__device__ __forceinline__ void mma_f16_ss(uint32_t d, uint64_t ad, uint64_t bd,
                                           uint32_t idesc, uint32_t en) {
    asm volatile(
        "{\n\t.reg .pred p;\n\tsetp.ne.u32 p, %4, 0;\n\t"
        "tcgen05.mma.cta_group::1.kind::f16 [%0], %1, %2, %3, {%5, %5, %5, %5}, p;\n\t}"
        :: "r"(d), "l"(ad), "l"(bd), "r"(idesc), "r"(en), "r"(0u) : "memory");
}
__device__ __forceinline__ void tc_commit(uint32_t mbar) {
    asm volatile(
        "tcgen05.commit.cta_group::1.mbarrier::arrive::one.shared::cluster.b64 [%0];"
        :: "r"(mbar) : "memory");
}
#define TC_FENCE_AFTER()  asm volatile("tcgen05.fence::after_thread_sync;" ::: "memory")
#define TC_WAIT_LD()      asm volatile("tcgen05.wait::ld.sync.aligned;" ::: "memory")
#define FENCE_ASYNC()     asm volatile("fence.proxy.async.shared::cta;" ::: "memory")
#define TCGEN05_LD_32X32B_X32(r, tmem_addr) \
    asm volatile( \
        "tcgen05.ld.sync.aligned.32x32b.x32.b32 " \
        "{%0, %1, %2, %3, %4, %5, %6, %7, " \
        " %8, %9, %10, %11, %12, %13, %14, %15, " \
        " %16, %17, %18, %19, %20, %21, %22, %23, " \
        " %24, %25, %26, %27, %28, %29, %30, %31}, [%32];" \
        : "=r"((r)[0]),  "=r"((r)[1]),  "=r"((r)[2]),  "=r"((r)[3]), \
          "=r"((r)[4]),  "=r"((r)[5]),  "=r"((r)[6]),  "=r"((r)[7]), \
          "=r"((r)[8]),  "=r"((r)[9]),  "=r"((r)[10]), "=r"((r)[11]), \
          "=r"((r)[12]), "=r"((r)[13]), "=r"((r)[14]), "=r"((r)[15]), \
          "=r"((r)[16]), "=r"((r)[17]), "=r"((r)[18]), "=r"((r)[19]), \
          "=r"((r)[20]), "=r"((r)[21]), "=r"((r)[22]), "=r"((r)[23]), \
          "=r"((r)[24]), "=r"((r)[25]), "=r"((r)[26]), "=r"((r)[27]), \
          "=r"((r)[28]), "=r"((r)[29]), "=r"((r)[30]), "=r"((r)[31]) \
        : "r"(tmem_addr))
#endif // HAS_TCGEN05

#define SWZ(o) ((o) ^ (((o) >> 3) & 0x70))
#define SMEM_DESC_BASE ((uint64_t(2) << 61) | (uint64_t(1) << 46) | (uint64_t(64) << 32) | (uint64_t(1) << 16))
#define MK_DESC(addr) (SMEM_DESC_BASE | ((uint64_t)((addr) >> 4) & 0x3FFF))
#define MMA_IDESC   0x8200490u
#define IDESC_PV    0x8100490u

// ---------------- weight convert+transpose: W[K][N] -> o[N][2K] [hi|lo] ------
__device__ __forceinline__ void conv_w_body(const float* __restrict__ W,
                                            __nv_bfloat16* __restrict__ o, int K, int N) {
    __shared__ float t[32][33];
    int n0 = blockIdx.x * 32, k0 = blockIdx.y * 32;
    if (n0 >= N || k0 >= K) return;
    int tx = threadIdx.x, ty = threadIdx.y; // 32 x 8
    #pragma unroll
    for (int i = 0; i < 4; i++)
        t[ty + 8 * i][tx] = W[(size_t)(k0 + ty + 8 * i) * N + n0 + tx];
    __syncthreads();
    size_t K2 = 2 * (size_t)K;
    #pragma unroll
    for (int i = 0; i < 4; i++) {
        int nn = ty + 8 * i, kk = tx;
        float x = t[kk][nn];
        __nv_bfloat16 hi, lo; split_bf16(x, hi, lo);
        size_t base = (size_t)(n0 + nn) * K2 + (size_t)(k0 + kk);
        o[base] = hi; o[base + K] = lo;
    }
}
__global__ void conv_w4_kernel(const float* __restrict__ w0, const float* __restrict__ w1,
                               const float* __restrict__ w2, const float* __restrict__ w3,
                               __nv_bfloat16* o0, __nv_bfloat16* o1,
                               __nv_bfloat16* o2, __nv_bfloat16* o3) {
    const float* W = (blockIdx.z == 0) ? w0 : (blockIdx.z == 1) ? w1 : (blockIdx.z == 2) ? w2 : w3;
    __nv_bfloat16* O = (blockIdx.z == 0) ? o0 : (blockIdx.z == 1) ? o1 : (blockIdx.z == 2) ? o2 : o3;
    conv_w_body(W, O, TB_D, TB_D);
}
__global__ void conv_win_kernel(const float* __restrict__ w_in, __nv_bfloat16* win3) {
    conv_w_body(w_in, win3, TB_D, TB_F);
}
__global__ void conv_wout_kernel(const float* __restrict__ w_out, __nv_bfloat16* wout3) {
    conv_w_body(w_out, wout3, TB_F, TB_D);
}

// ---------------- srmsnorm -> split-bf16 [hi(D)|lo(D)] -----------------------
__global__ void srmsnorm3_kernel(const float* __restrict__ x, __nv_bfloat16* __restrict__ y) {
    int row = blockIdx.x;
    int tid = threadIdx.x;
    const float* xr = x + (size_t)row * TB_D;
    float4 v = *(const float4*)(xr + tid * 4);
    float ss = v.x*v.x + v.y*v.y + v.z*v.z + v.w*v.w;
    #pragma unroll
    for (int o = 16; o; o >>= 1) ss += __shfl_xor_sync(0xffffffffu, ss, o);
    __shared__ float wred[8];
    __shared__ float s_scale;
    if ((tid & 31) == 0) wred[tid >> 5] = ss;
    __syncthreads();
    if (tid == 0) {
        float tot = 0.f;
        #pragma unroll
        for (int i = 0; i < 8; i++) tot += wred[i];
        s_scale = 32.0f / fmaxf(sqrtf(tot), 1e-12f);
    }
    __syncthreads();
    float sc = s_scale;
    float vals[4] = {v.x * sc, v.y * sc, v.z * sc, v.w * sc};
    __nv_bfloat16 hi[4], lo[4];
    #pragma unroll
    for (int j = 0; j < 4; j++) split_bf16(vals[j], hi[j], lo[j]);
    uint2 h2 = pack4bf(hi[0], hi[1], hi[2], hi[3]);
    uint2 l2 = pack4bf(lo[0], lo[1], lo[2], lo[3]);
    size_t base = (size_t)row * TB_D2 + tid * 4;
    *(uint2*)(y + base)        = h2;
    *(uint2*)(y + base + TB_D) = l2;
}

// ---------------- R13 tcgen05 split-bf16 GEMM (proven best) ------------------
#define ST_A 32768
#define ST_B 65536
#define STAGE2 (ST_A + ST_B)            // 96KB
#define GEMM_SMEM (2 * STAGE2 + 1024)   // 193KB

__device__ __forceinline__ void tc_gemm_body(
    const __nv_bfloat16* __restrict__ A2, const __nv_bfloat16* __restrict__ B2,
    const float* __restrict__ res, void* __restrict__ Cout,
    int N, int K, int m0, int n0, int epi)
{
    int K2 = 2 * K;
#if HAS_TCGEN05
    extern __shared__ char dsm_raw[];
    __shared__ uint32_t s_tmem;
    __shared__ __align__(8) uint64_t s_bars[4]; // full[2], empty[2]
    char* dsp = (char*)(((uintptr_t)dsm_raw + 1023) & ~(uintptr_t)1023);
    uint32_t dsm = smem_u32(dsp);
    int tid = threadIdx.x, wid = tid >> 5, lane = tid & 31;

    if (wid == 0) {
        asm volatile("tcgen05.alloc.cta_group::1.sync.aligned.shared::cta.b32 [%0], %1;"
                     :: "r"(smem_u32((void*)&s_tmem)), "r"(256u) : "memory");
    }
    if (tid == 0) {
        #pragma unroll
        for (int s = 0; s < 2; s++) {
            mbar_init(smem_u32(&s_bars[s]), 128);
            mbar_init(smem_u32(&s_bars[2 + s]), 1);
        }
    }
    __syncthreads();
    uint32_t tmem = s_tmem;

    const __nv_bfloat16* Ab = A2 + (size_t)m0 * K2;
    const __nv_bfloat16* Bb = B2 + (size_t)n0 * K2;
    int nch = K >> 6;    // even

    if (wid < 4) {
        for (int c = 0; c < nch; c++) {
            int s = c & 1;
            uint32_t sb = dsm + s * STAGE2;
            if (c >= 2)
                mbar_wait(smem_u32(&s_bars[2 + s]), ((c >> 1) - 1) & 1);
            const __nv_bfloat16* ga = Ab + (c << 6);
            const __nv_bfloat16* gb = Bb + (c << 6);
            #pragma unroll
            for (int i = 0; i < 8; i++) {
                int u = tid + (i << 7);
                int r = u >> 3, q = u & 7;
                cp_async16(sb + SWZ(r * 128 + q * 16), ga + (size_t)r * K2 + q * 8);
            }
            #pragma unroll
            for (int i = 0; i < 8; i++) {
                int u = tid + (i << 7);
                int r = u >> 3, q = u & 7;
                cp_async16(sb + 16384 + SWZ(r * 128 + q * 16), ga + (size_t)r * K2 + K + q * 8);
            }
            #pragma unroll
            for (int i = 0; i < 16; i++) {
                int u = tid + (i << 7);
                int r = u >> 3, q = u & 7;
                cp_async16(sb + 32768 + SWZ(r * 128 + q * 16), gb + (size_t)r * K2 + q * 8);
            }
            #pragma unroll
            for (int i = 0; i < 16; i++) {
                int u = tid + (i << 7);
                int r = u >> 3, q = u & 7;
                cp_async16(sb + 65536 + SWZ(r * 128 + q * 16), gb + (size_t)r * K2 + K + q * 8);
            }
            cp_async_arrive(smem_u32(&s_bars[s]));
        }
        uint32_t pe = ((uint32_t)(nch >> 1) - 1u) & 1u;
        #pragma unroll
        for (int s = 0; s < 2; s++)
            mbar_wait(smem_u32(&s_bars[2 + s]), pe);
    } else if (wid == 7) {
        for (int c = 0; c < nch; c++) {
            int s = c & 1;
            uint32_t sb = dsm + s * STAGE2;
            mbar_wait(smem_u32(&s_bars[s]), (c >> 1) & 1);
            if (elect_one()) {
                uint64_t ah  = MK_DESC(sb);
                uint64_t al  = MK_DESC(sb + 16384);
                uint64_t bh0 = MK_DESC(sb + 32768);
                uint64_t bh1 = MK_DESC(sb + 49152);
                uint64_t bl0 = MK_DESC(sb + 65536);
                uint64_t bl1 = MK_DESC(sb + 81920);
                #pragma unroll
                for (int seg = 0; seg < 3; seg++) {
                    uint64_t a  = (seg == 1) ? al : ah;
                    uint64_t b0 = (seg == 2) ? bl0 : bh0;
                    uint64_t b1 = (seg == 2) ? bl1 : bh1;
                    #pragma unroll
                    for (int k = 0; k < 4; k++) {
                        uint32_t en = (c | seg | k) ? 1u : 0u;
                        mma_f16_ss(tmem,       a + 2*k, b0 + 2*k, MMA_IDESC, en);
                        mma_f16_ss(tmem + 128, a + 2*k, b1 + 2*k, MMA_IDESC, en);
                    }
                }
                tc_commit(smem_u32(&s_bars[2 + s]));   // ONE commit per group
            }
        }
    }
    __syncthreads();
    TC_FENCE_AFTER();

    int sub = wid & 3, half = wid >> 2;
    int mrow = m0 + sub * 32 + lane;
    for (int cb = 0; cb < 128; cb += 32) {
        uint32_t dr[32];
        TCGEN05_LD_32X32B_X32(dr, tmem + half * 128 + cb);
        TC_WAIT_LD();
        int n = n0 + half * 128 + cb;
        if (epi == 2) {
            __nv_bfloat16* C = (__nv_bfloat16*)Cout;
            size_t rb = (size_t)mrow * (2 * (size_t)N);
            __nv_bfloat16 hiA[32], loA[32];
            #pragma unroll
            for (int j = 0; j < 32; j++) {
                float f = gelu_tanh(__uint_as_float(dr[j]));
                split_bf16(f, hiA[j], loA[j]);
            }
            uint4* ph = (uint4*)(C + rb + n);
            uint4* pl = (uint4*)(C + rb + (size_t)N + n);
            #pragma unroll
            for (int t2 = 0; t2 < 4; t2++) {
                ph[t2] = ((uint4*)hiA)[t2];
                pl[t2] = ((uint4*)loA)[t2];
            }
        } else if (epi == 3 || epi == 4) {
            __nv_bfloat16* C = (__nv_bfloat16*)Cout;
            int bb = mrow >> 11, tl = mrow & 2047;
            int head = n >> 6, d0 = n & 63;
            __nv_bfloat16 hiA[32], loA[32];
            #pragma unroll
            for (int j = 0; j < 32; j++)
                split_bf16(__uint_as_float(dr[j]), hiA[j], loA[j]);
            __nv_bfloat16* dst = C + (((size_t)(bb * 16 + head)) * 2048 + tl) * 128;
            uint4* ph = (uint4*)(dst + d0);
            uint4* pl = (uint4*)(dst + 64 + d0);
            #pragma unroll
            for (int t2 = 0; t2 < 4; t2++) {
                ph[t2] = ((uint4*)hiA)[t2];
                pl[t2] = ((uint4*)loA)[t2];
            }
        } else if (epi == 5) {
            // V transposed: vt3[b*16+h][128 d-rows (hi 0..63, lo 64..127)][2048]
            __nv_bfloat16* C = (__nv_bfloat16*)Cout;
            int bb = mrow >> 11;
            int head = n >> 6, d0 = n & 63;
            int tl0 = (m0 & 2047) + sub * 32;
            __nv_bfloat16 hiA[32], loA[32];
            #pragma unroll
            for (int j = 0; j < 32; j++)
                split_bf16(__uint_as_float(dr[j]), hiA[j], loA[j]);
            uint16_t* sc  = (uint16_t*)(dsp + (size_t)wid * 4352);
            uint16_t* scl = sc + 1088;
            #pragma unroll
            for (int j = 0; j < 32; j++) {
                sc [lane * 34 + j] = __bfloat16_as_ushort(hiA[j]);
                scl[lane * 34 + j] = __bfloat16_as_ushort(loA[j]);
            }
            __syncwarp();
            uint32_t wh[16], wl[16];
            #pragma unroll
            for (int g = 0; g < 16; g++) {
                wh[g] = (uint32_t)sc [(2*g) * 34 + lane] | ((uint32_t)sc [(2*g+1) * 34 + lane] << 16);
                wl[g] = (uint32_t)scl[(2*g) * 34 + lane] | ((uint32_t)scl[(2*g+1) * 34 + lane] << 16);
            }
            size_t base_hb = (size_t)(bb * 16 + head) * 262144;
            __nv_bfloat16* dh = C + base_hb + (size_t)(d0 + lane) * 2048 + tl0;
            __nv_bfloat16* dl = C + base_hb + (size_t)(64 + d0 + lane) * 2048 + tl0;
            #pragma unroll
            for (int g = 0; g < 4; g++) {
                ((uint4*)dh)[g] = ((uint4*)wh)[g];
                ((uint4*)dl)[g] = ((uint4*)wl)[g];
            }
            __syncwarp();
        } else {
            float* C = (float*)Cout;
            size_t base = (size_t)mrow * N + n;
            #pragma unroll
            for (int j = 0; j < 32; j += 4) {
                float4 v = make_float4(__uint_as_float(dr[j]),   __uint_as_float(dr[j+1]),
                                       __uint_as_float(dr[j+2]), __uint_as_float(dr[j+3]));
                if (epi == 1) {
                    float4 r4 = *(const float4*)(res + base + j);
                    v.x += r4.x; v.y += r4.y; v.z += r4.z; v.w += r4.w;
                }
                *(float4*)(C + base + j) = v;
            }
        }
    }
    __syncthreads();
    if (wid == 0) {
        asm volatile("tcgen05.relinquish_alloc_permit.cta_group::1.sync.aligned;");
        asm volatile("tcgen05.dealloc.cta_group::1.sync.aligned.b32 %0, %1;"
                     :: "r"(tmem), "r"(256u));
    }
#else
    // ---------------- SIMT fallback (non-sm_103a cubin only) -----------------
    int tid = threadIdx.x;
    int n_c = n0 + tid;
    for (int m = 0; m < 128; m++) {
        int mrow = m0 + m;
        const __nv_bfloat16* ar = A2 + (size_t)mrow * K2;
        const __nv_bfloat16* br = B2 + (size_t)n_c * K2;
        float acc = 0.f;
        for (int k = 0; k < K; k++) {
            float ah = __bfloat162float(ar[k]), al = __bfloat162float(ar[K + k]);
            float bh = __bfloat162float(br[k]), bl = __bfloat162float(br[K + k]);
            acc += ah * bh + al * bh + ah * bl;
        }
        if (epi == 2) {
            __nv_bfloat16* C = (__nv_bfloat16*)Cout;
            size_t base = (size_t)mrow * (2 * (size_t)N);
            float f = gelu_tanh(acc);
            __nv_bfloat16 hi, lo; split_bf16(f, hi, lo);
            C[base + n_c] = hi; C[base + N + n_c] = lo;
        } else if (epi == 3 || epi == 4) {
            __nv_bfloat16* C = (__nv_bfloat16*)Cout;
            int bb = mrow >> 11, tl = mrow & 2047;
            int head = n_c >> 6, d = n_c & 63;
            __nv_bfloat16 hi, lo; split_bf16(acc, hi, lo);
            size_t base = (((size_t)(bb * 16 + head)) * 2048 + tl) * 128;
            C[base + d] = hi; C[base + 64 + d] = lo;
        } else if (epi == 5) {
            __nv_bfloat16* C = (__nv_bfloat16*)Cout;
            int bb = mrow >> 11, tl = mrow & 2047;
            int head = n_c >> 6, d = n_c & 63;
            __nv_bfloat16 hi, lo; split_bf16(acc, hi, lo);
            size_t base = (size_t)(bb * 16 + head) * 262144;
            C[base + (size_t)d * 2048 + tl] = hi;
            C[base + (size_t)(64 + d) * 2048 + tl] = lo;
        } else {
            float* C = (float*)Cout;
            size_t base = (size_t)mrow * N;
            if (epi == 1) acc += res[base + n_c];
            C[base + n_c] = acc;
        }
    }
#endif
}

template<int EPI>
__global__ __launch_bounds__(256, 1) void tc_gemm(
    const __nv_bfloat16* __restrict__ A2, const __nv_bfloat16* __restrict__ B2,
    const float* __restrict__ res, void* __restrict__ C, int N, int K)
{
    tc_gemm_body(A2, B2, res, C, N, K, blockIdx.y * 128, blockIdx.x * 256, EPI);
}

__global__ __launch_bounds__(256, 1) void tc_gemm_qkv(
    const __nv_bfloat16* __restrict__ A2,
    const __nv_bfloat16* __restrict__ b0, const __nv_bfloat16* __restrict__ b1,
    const __nv_bfloat16* __restrict__ b2,
    __nv_bfloat16* __restrict__ c0, __nv_bfloat16* __restrict__ c1,
    __nv_bfloat16* __restrict__ c2)
{
    const __nv_bfloat16* B2 = (blockIdx.z == 0) ? b0 : ((blockIdx.z == 1) ? b1 : b2);
    __nv_bfloat16* C = (blockIdx.z == 0) ? c0 : ((blockIdx.z == 1) ? c1 : c2);
    tc_gemm_body(A2, B2, nullptr, C, TB_D, TB_D,
                 blockIdx.y * 128, blockIdx.x * 256, 3 + (int)blockIdx.z);
}

// ---------------- tcgen05 causal flash attention ------------------------------
// R16b: exp2-domain softmax (S scaled by 0.125*log2e at read), diagonal-tile
// mask specialization, truncation split for P. Barrier protocol = R13 (proven).
#define ATT_DSMEM (192 * 1024 + 1024)
#define SCALE_L2E 0.18033688011112042f    // 0.125 * log2(e)

__global__ __launch_bounds__(256, 1) void tc_attn(
    const __nv_bfloat16* __restrict__ q3, const __nv_bfloat16* __restrict__ k3,
    const __nv_bfloat16* __restrict__ vt3, __nv_bfloat16* __restrict__ att3)
{
    int qtile = 15 - (int)blockIdx.x;          // heavy tiles first
    int h = blockIdx.y, b = blockIdx.z;
    int ntiles = qtile + 1;
    int q0 = qtile * 128;
    size_t hb = (size_t)b * 16 + h;
    const __nv_bfloat16* qh = q3 + hb * (size_t)2048 * 128;
    const __nv_bfloat16* kh = k3 + hb * (size_t)2048 * 128;
    const __nv_bfloat16* vh = vt3 + hb * (size_t)262144;
#if HAS_TCGEN05
    extern __shared__ char dsm_raw[];
    __shared__ uint32_t s_tmem;
    __shared__ __align__(8) uint64_t bars[7]; // bK0 bK1 bV bP bO bSK0 bSK1
    char* dsmp = (char*)(((uintptr_t)dsm_raw + 1023) & ~(uintptr_t)1023);
    uint32_t dsm = smem_u32(dsmp);
    uint32_t Q0c = dsm, Q1c = dsm + 16384;
    uint32_t Kst = dsm + 32768;
    uint32_t Vt  = dsm + 98304;
    uint32_t Pb  = dsm + 131072;
    uint32_t bK[2]  = { smem_u32(&bars[0]), smem_u32(&bars[1]) };
    uint32_t bV = smem_u32(&bars[2]), bP = smem_u32(&bars[3]);
    uint32_t bO = smem_u32(&bars[4]);
    uint32_t bSK[2] = { smem_u32(&bars[5]), smem_u32(&bars[6]) };
    int tid = threadIdx.x, wid = tid >> 5, lane = tid & 31;

    if (wid == 0) {
        asm volatile("tcgen05.alloc.cta_group::1.sync.aligned.shared::cta.b32 [%0], %1;"
                     :: "r"(smem_u32((void*)&s_tmem)), "r"(256u) : "memory");
    }
    if (tid == 0) {
        mbar_init(bK[0], 64); mbar_init(bK[1], 64);
        mbar_init(bV, 32); mbar_init(bP, 128); mbar_init(bO, 1);
        mbar_init(bSK[0], 1); mbar_init(bSK[1], 1);
    }
    __syncthreads();
    uint32_t tmem = s_tmem;

    if (wid >= 4) {
        int t4 = tid - 128;
        #pragma unroll
        for (int i = 0; i < 8; i++) {
            int u = t4 + 128 * i, r = u >> 3, q = u & 7;
            cp_async16(Q0c + SWZ(r * 128 + q * 16), qh + (size_t)(q0 + r) * 128 + q * 8);
        }
        #pragma unroll
        for (int i = 0; i < 8; i++) {
            int u = t4 + 128 * i, r = u >> 3, q = u & 7;
            cp_async16(Q1c + SWZ(r * 128 + q * 16), qh + (size_t)(q0 + r) * 128 + 64 + q * 8);
        }
        asm volatile("cp.async.wait_all;" ::: "memory");
    }
    __syncthreads();

    if (wid == 4 || wid == 5) {
        int t2 = tid - 128;
        for (int t = 0; t < ntiles; t++) {
            if (t >= 2) mbar_wait(bSK[t & 1], ((t >> 1) - 1) & 1);
            uint32_t Ks = Kst + (t & 1) * 32768;
            int k0 = t * 128;
            #pragma unroll
            for (int i = 0; i < 16; i++) {
                int u = t2 + 64 * i, r = u >> 3, q = u & 7;
                cp_async16(Ks + SWZ(r * 128 + q * 16), kh + (size_t)(k0 + r) * 128 + q * 8);
            }
            #pragma unroll
            for (int i = 0; i < 16; i++) {
                int u = t2 + 64 * i, r = u >> 3, q = u & 7;
                cp_async16(Ks + 16384 + SWZ(r * 128 + q * 16), kh + (size_t)(k0 + r) * 128 + 64 + q * 8);
            }
            cp_async_arrive(bK[t & 1]);
        }
    } else if (wid == 6) {
        int t3 = tid - 192;
        for (int t = 0; t < ntiles; t++) {
            if (t >= 1) mbar_wait(bO, (t - 1) & 1);
            int k0 = t * 128;
            #pragma unroll
            for (int p = 0; p < 2; p++)
                #pragma unroll
                for (int cc = 0; cc < 2; cc++) {
                    uint32_t cb = Vt + (p * 2 + cc) * 8192;
                    #pragma unroll
                    for (int i = 0; i < 16; i++) {
                        int u = t3 + 32 * i, r = u >> 3, q = u & 7;
                        cp_async16(cb + SWZ(r * 128 + q * 16),
                                   vh + (size_t)(p * 64 + r) * 2048 + k0 + cc * 64 + q * 8);
                    }
                }
            cp_async_arrive(bV);
        }
    } else if (wid == 7) {
        for (int t = 0; t < ntiles; t++) {
            mbar_wait(bK[t & 1], (t >> 1) & 1);
            if (elect_one()) {
                uint32_t Ks = Kst + (t & 1) * 32768;
                uint64_t qd[3] = { MK_DESC(Q0c), MK_DESC(Q1c), MK_DESC(Q0c) };
                uint64_t kd[3] = { MK_DESC(Ks), MK_DESC(Ks), MK_DESC(Ks + 16384) };
                #pragma unroll
                for (int seg = 0; seg < 3; seg++)
                    #pragma unroll
                    for (int s = 0; s < 4; s++)
                        mma_f16_ss(tmem, qd[seg] + 2 * s, kd[seg] + 2 * s,
                                   MMA_IDESC, (seg | s) ? 1u : 0u);
                tc_commit(bSK[t & 1]);
            }
            mbar_wait(bV, t & 1);
            mbar_wait(bP, t & 1);
            if (elect_one()) {
                uint64_t pa[3][2] = {
                    { MK_DESC(Pb),         MK_DESC(Pb + 16384) },
                    { MK_DESC(Pb + 32768), MK_DESC(Pb + 49152) },
                    { MK_DESC(Pb),         MK_DESC(Pb + 16384) } };
                const int vpart[3] = { 0, 0, 1 };
                #pragma unroll
                for (int seg = 0; seg < 3; seg++)
                    #pragma unroll
                    for (int s = 0; s < 8; s++) {
                        int cc = s >> 2;
                        mma_f16_ss(tmem + 128,
                                   pa[seg][cc] + 2 * (s & 3),
                                   MK_DESC(Vt + (vpart[seg] * 2 + cc) * 8192) + 2 * (s & 3),
                                   IDESC_PV, (seg | s) ? 1u : 0u);
                    }
                tc_commit(bO);
            }
        }
    } else {
        // ---------------- compute warps 0-3: lane owns row ---------------------
        int rloc = wid * 32 + lane;
        int rg = q0 + rloc;
        float m = -1e30f, l = 0.f, alpha_prev = 0.f;
        float O[64];
        #pragma unroll
        for (int j = 0; j < 64; j++) O[j] = 0.f;

        for (int t = 0; t < ntiles; t++) {
            mbar_wait(bSK[t & 1], (t >> 1) & 1);   // S(t) ready
            TC_FENCE_AFTER();
            // read S once into registers, log2-domain scale; mask only on the
            // diagonal tile (t == qtile); track running max inline
            float s[128];
            float mt = -1e30f;
            if (t == qtile) {
                int lim = rg - t * 128;
                #pragma unroll
                for (int cb = 0; cb < 4; cb++) {
                    uint32_t dr[32];
                    TCGEN05_LD_32X32B_X32(dr, tmem + cb * 32);
                    TC_WAIT_LD();
                    #pragma unroll
                    for (int j = 0; j < 32; j++) {
                        int c = cb * 32 + j;
                        float v = (c <= lim) ? __uint_as_float(dr[j]) * SCALE_L2E : -1e30f;
                        s[c] = v;
                        mt = fmaxf(mt, v);
                    }
                }
            } else {
                #pragma unroll
                for (int cb = 0; cb < 4; cb++) {
                    uint32_t dr[32];
                    TCGEN05_LD_32X32B_X32(dr, tmem + cb * 32);
                    TC_WAIT_LD();
                    #pragma unroll
                    for (int j = 0; j < 32; j++) {
                        int c = cb * 32 + j;
                        float v = __uint_as_float(dr[j]) * SCALE_L2E;
                        s[c] = v;
                        mt = fmaxf(mt, v);
                    }
                }
            }
            float mn = fmaxf(m, mt);
            float al = exp2f(m - mn);
            // fold previous PV result BEFORE writing P (PV(t-1) reads Pb)
            if (t > 0) {
                mbar_wait(bO, (t - 1) & 1);
                TC_FENCE_AFTER();
                uint32_t du[32];
                TCGEN05_LD_32X32B_X32(du, tmem + 128);
                TC_WAIT_LD();
                #pragma unroll
                for (int j = 0; j < 32; j++)
                    O[j] = O[j] * alpha_prev + __uint_as_float(du[j]);
                TCGEN05_LD_32X32B_X32(du, tmem + 160);
                TC_WAIT_LD();
                #pragma unroll
                for (int j = 0; j < 32; j++)
                    O[32 + j] = O[32 + j] * alpha_prev + __uint_as_float(du[j]);
            }
            // exp2 + truncation-split-store P into smem
            float ps = 0.f;
            #pragma unroll
            for (int c = 0; c < 128; c += 4) {
                float p0 = exp2f(s[c]     - mn);
                float p1 = exp2f(s[c + 1] - mn);
                float p2 = exp2f(s[c + 2] - mn);
                float p3 = exp2f(s[c + 3] - mn);
                ps += (p0 + p1) + (p2 + p3);
                uint16_t h0, h1, h2, h3;
                __nv_bfloat16 l0, l1, l2, l3;
                split_bf16_trunc(p0, h0, l0); split_bf16_trunc(p1, h1, l1);
                split_bf16_trunc(p2, h2, l2); split_bf16_trunc(p3, h3, l3);
                uint2 hv;
                hv.x = (uint32_t)h0 | ((uint32_t)h1 << 16);
                hv.y = (uint32_t)h2 | ((uint32_t)h3 << 16);
                uint2 lv = pack4bf(l0, l1, l2, l3);
                int subo = (c >> 6) * 16384;
                uint32_t so = SWZ(rloc * 128 + (c & 63) * 2);
                *(uint2*)(dsmp + 131072 + subo + so) = hv;   // Phi
                *(uint2*)(dsmp + 163840 + subo + so) = lv;   // Plo
            }
            l = l * al + ps;
            alpha_prev = al;
            m = mn;
            FENCE_ASYNC();
            mbar_arrive(bP);
        }
        mbar_wait(bO, (ntiles - 1) & 1);
        TC_FENCE_AFTER();
        {
            uint32_t du[32];
            TCGEN05_LD_32X32B_X32(du, tmem + 128);
            TC_WAIT_LD();
            #pragma unroll
            for (int j = 0; j < 32; j++)
                O[j] = O[j] * alpha_prev + __uint_as_float(du[j]);
            TCGEN05_LD_32X32B_X32(du, tmem + 160);
            TC_WAIT_LD();
            #pragma unroll
            for (int j = 0; j < 32; j++)
                O[32 + j] = O[32 + j] * alpha_prev + __uint_as_float(du[j]);
        }
        float inv = 1.0f / l;
        __nv_bfloat16 hi[64], lo[64];
        #pragma unroll
        for (int j = 0; j < 64; j++) split_bf16(O[j] * inv, hi[j], lo[j]);
        size_t rb = ((size_t)b * 2048 + rg) * TB_D2 + h * 64;
        uint4* ph = (uint4*)(att3 + rb);
        uint4* pl = (uint4*)(att3 + rb + TB_D);
        #pragma unroll
        for (int i = 0; i < 8; i++) {
            ph[i] = ((uint4*)hi)[i];
            pl[i] = ((uint4*)lo)[i];
        }
    }
    __syncthreads();
    if (wid == 0) {
        asm volatile("tcgen05.relinquish_alloc_permit.cta_group::1.sync.aligned;");
        asm volatile("tcgen05.dealloc.cta_group::1.sync.aligned.b32 %0, %1;"
                     :: "r"(tmem), "r"(256u));
    }
#else
    int tid = threadIdx.x;
    if (tid < 128) {
        int rg = q0 + tid;
        float q[64];
        #pragma unroll
        for (int d = 0; d < 64; d++)
            q[d] = __bfloat162float(qh[(size_t)rg * 128 + d]) +
                   __bfloat162float(qh[(size_t)rg * 128 + 64 + d]);
        float m = -1e30f;
        for (int k = 0; k <= rg; k++) {
            float s = 0.f;
            for (int d = 0; d < 64; d++)
                s += q[d] * (__bfloat162float(kh[(size_t)k * 128 + d]) +
                             __bfloat162float(kh[(size_t)k * 128 + 64 + d]));
            m = fmaxf(m, s * 0.125f);
        }
        float l = 0.f, O[64];
        for (int d = 0; d < 64; d++) O[d] = 0.f;
        for (int k = 0; k <= rg; k++) {
            float s = 0.f;
            for (int d = 0; d < 64; d++)
                s += q[d] * (__bfloat162float(kh[(size_t)k * 128 + d]) +
                             __bfloat162float(kh[(size_t)k * 128 + 64 + d]));
            float p = expf(s * 0.125f - m);
            l += p;
            for (int d = 0; d < 64; d++)
                O[d] += p * (__bfloat162float(vh[(size_t)d * 2048 + k]) +
                             __bfloat162float(vh[(size_t)(64 + d) * 2048 + k]));
        }
        float inv = 1.0f / l;
        size_t rb = ((size_t)b * 2048 + rg) * TB_D2 + h * 64;
        for (int d = 0; d < 64; d++) {
            __nv_bfloat16 hi, lo; split_bf16(O[d] * inv, hi, lo);
            att3[rb + d] = hi; att3[rb + TB_D + d] = lo;
        }
    }
#endif
}

// ---------------- launch ------------------------------------------------------
extern "C" void kernel_launch(void* const* d_in, const int* in_sizes, int n_in,
                              void* d_out, int out_size) {
    const float* x     = (const float*)d_in[0];
    const float* wq    = (const float*)d_in[1];
    const float* wk    = (const float*)d_in[2];
    const float* wv    = (const float*)d_in[3];
    const float* wo    = (const float*)d_in[4];
    const float* w_in  = (const float*)d_in[5];
    const float* w_out = (const float*)d_in[6];
    float* out = (float*)d_out;
    (void)in_sizes; (void)n_in; (void)out_size;

    __nv_bfloat16 *xn3, *att3, *ff3, *q3, *k3, *vt3;
    __nv_bfloat16 *wq3, *wk3, *wv3, *wo3, *win3, *wout3;
    float *h;
    cudaGetSymbolAddress((void**)&xn3,  g_xn3);
    cudaGetSymbolAddress((void**)&att3, g_att3);
    cudaGetSymbolAddress((void**)&ff3,  g_ff3);
    cudaGetSymbolAddress((void**)&q3,   g_q3);
    cudaGetSymbolAddress((void**)&k3,   g_k3);
    cudaGetSymbolAddress((void**)&vt3,  g_vt3);
    cudaGetSymbolAddress((void**)&h,    g_h);
    cudaGetSymbolAddress((void**)&wq3,  g_wq3);
    cudaGetSymbolAddress((void**)&wk3,  g_wk3);
    cudaGetSymbolAddress((void**)&wv3,  g_wv3);
    cudaGetSymbolAddress((void**)&wo3,  g_wo3);
    cudaGetSymbolAddress((void**)&win3, g_win3);
    cudaGetSymbolAddress((void**)&wout3, g_wout3);

    cudaFuncSetAttribute(tc_attn,     cudaFuncAttributeMaxDynamicSharedMemorySize, ATT_DSMEM);
    cudaFuncSetAttribute(tc_gemm_qkv, cudaFuncAttributeMaxDynamicSharedMemorySize, GEMM_SMEM);
    cudaFuncSetAttribute(tc_gemm<1>,  cudaFuncAttributeMaxDynamicSharedMemorySize, GEMM_SMEM);
    cudaFuncSetAttribute(tc_gemm<2>,  cudaFuncAttributeMaxDynamicSharedMemorySize, GEMM_SMEM);

    dim3 cwb(32, 8);
    conv_w4_kernel<<<dim3(32, 32, 4), cwb>>>(wq, wk, wv, wo, wq3, wk3, wv3, wo3);   // 1
    conv_win_kernel<<<dim3(128, 32), cwb>>>(w_in, win3);                            // 2
    conv_wout_kernel<<<dim3(32, 128), cwb>>>(w_out, wout3);                         // 3
    srmsnorm3_kernel<<<TB_T, 256>>>(x, xn3);                                        // 4
    tc_gemm_qkv<<<dim3(TB_D / 256, TB_T / 128, 3), 256, GEMM_SMEM>>>(               // 5
        xn3, wq3, wk3, wv3, q3, k3, vt3);
    tc_attn<<<dim3(16, TB_H, TB_B), 256, ATT_DSMEM>>>(q3, k3, vt3, att3);           // 6
    tc_gemm<1><<<dim3(TB_D / 256, TB_T / 128), 256, GEMM_SMEM>>>(                   // 7
        att3, wo3, x, h, TB_D, TB_D);
    srmsnorm3_kernel<<<TB_T, 256>>>(h, xn3);                                        // 8
    tc_gemm<2><<<dim3(TB_F / 256, TB_T / 128), 256, GEMM_SMEM>>>(                   // 9
        xn3, win3, nullptr, ff3, TB_F, TB_D);
    tc_gemm<1><<<dim3(TB_D / 256, TB_T / 128), 256, GEMM_SMEM>>>(                   // 10
        ff3, wout3, h, out, TB_D, TB_F);
}